// round 1
// baseline (speedup 1.0000x reference)
#include <cuda_runtime.h>
#include <math.h>

// Problem constants (fixed shapes for this problem instance)
#define B_    32
#define H_    6
#define W_    2400
#define C_    64
#define OV_   4
#define G_    3
#define NVQ_  6
#define K_    1024
#define D_    8
#define FIX_  384           // H*C
#define GD_   512           // FIX*OV/G
#define T_    600           // W/OV
#define NPG   (B_*T_)       // 19200 points per group
#define ZQ_SIZE  (B_*H_*W_*C_)     // 29491200
#define IDX_SIZE (B_*NVQ_*G_*T_)   // 345600

// Scratch (no allocations allowed)
__device__ float g_en [G_*NVQ_*K_*D_];   // normalized codebooks
__device__ float g_zd [G_*NPG*D_];       // proj_down output
__device__ float g_zqd[G_*NPG*D_];       // quantized (pre proj_up)
__device__ float g_partial[512];         // per-block loss partials

// ---------------------------------------------------------------------------
// K1: normalize codebook rows: en = cb / max(||cb||, 1e-12)
// ---------------------------------------------------------------------------
__global__ void k_norm(const float* __restrict__ cb) {
    int r = blockIdx.x * blockDim.x + threadIdx.x;
    if (r >= G_*NVQ_*K_) return;
    const float* src = cb + (size_t)r * D_;
    float v[8]; float ss = 0.f;
#pragma unroll
    for (int d = 0; d < 8; d++) { v[d] = src[d]; ss = fmaf(v[d], v[d], ss); }
    float inv = 1.0f / fmaxf(sqrtf(ss), 1e-12f);
#pragma unroll
    for (int d = 0; d < 8; d++) g_en[r*8 + d] = v[d] * inv;
}

// ---------------------------------------------------------------------------
// K2: pre_process (fold/permute) fused with proj_down.
// Block = (b, tile of 8 t). smem: z tile (transposed) + pd, padded strides
// chosen for conflict-free compute-phase reads.
// ---------------------------------------------------------------------------
#define SZ_STRIDE 1540   // 1536 + 4  -> t rows land on distinct banks
#define PD_STRIDE 520    // 512 + 8   -> gd rows land on distinct banks
#define K2_SMEM   ((8*SZ_STRIDE + 24*PD_STRIDE) * 4)   // 99200 bytes

__global__ void k_down(const float* __restrict__ ze, const float* __restrict__ pd) {
    extern __shared__ float sm[];
    float* sZ  = sm;                    // [8][SZ_STRIDE]
    float* sPD = sm + 8*SZ_STRIDE;      // [24][PD_STRIDE]
    int bid  = blockIdx.x;
    int b    = bid / (T_/8);
    int tblk = bid % (T_/8);
    int t0   = tblk * 8;
    int w0   = t0 * 4;
    int tid  = threadIdx.x;

    // load proj_down (G*D rows of 512) into smem
    for (int idx = tid; idx < G_*D_*GD_; idx += 256) {
        int gd = idx >> 9, j = idx & 511;
        sPD[gd*PD_STRIDE + j] = pd[idx];
    }
    // stage z tile: z_e[b, h*W + w, c] -> sZ[t_local][o*384 + c*6 + h]
#pragma unroll
    for (int h = 0; h < 6; h++) {
        const float* src = ze + ((size_t)(b*H_ + h)*W_ + w0) * C_;
        for (int e = tid; e < 32*64; e += 256) {
            int wl = e >> 6, c = e & 63;
            int tl = wl >> 2, o = wl & 3;
            sZ[tl*SZ_STRIDE + o*FIX_ + c*6 + h] = src[e];
        }
    }
    __syncthreads();

    if (tid < 192) {
        int gd = tid >> 3;          // 0..23  (g*8 + d)
        int tl = tid & 7;           // 0..7
        int g  = gd >> 3, d = gd & 7;
        const float4* zr = (const float4*)(sZ + tl*SZ_STRIDE + g*GD_);
        const float4* pr = (const float4*)(sPD + gd*PD_STRIDE);
        float a0 = 0.f, a1 = 0.f;
#pragma unroll 8
        for (int j = 0; j < 128; j += 2) {
            float4 z0 = zr[j],   p0 = pr[j];
            float4 z1 = zr[j+1], p1 = pr[j+1];
            a0 = fmaf(z0.x, p0.x, a0); a1 = fmaf(z0.y, p0.y, a1);
            a0 = fmaf(z0.z, p0.z, a0); a1 = fmaf(z0.w, p0.w, a1);
            a0 = fmaf(z1.x, p1.x, a0); a1 = fmaf(z1.y, p1.y, a1);
            a0 = fmaf(z1.z, p1.z, a0); a1 = fmaf(z1.w, p1.w, a1);
        }
        g_zd[((size_t)g*NPG + b*T_ + t0 + tl)*D_ + d] = a0 + a1;
    }
}

// ---------------------------------------------------------------------------
// K3: residual VQ. 1 thread = 1 point. Codebook for the current stream is
// broadcast from smem (all lanes read the same k -> conflict-free).
// argmax(cos sim) == argmax(r . en_k)  (positive scale invariance).
// Writes codes (as float) directly into d_out's index region.
// ---------------------------------------------------------------------------
__global__ void __launch_bounds__(128) k_rvq(float* __restrict__ out_codes) {
    __shared__ float sEn[K_*D_];     // 32 KB
    __shared__ float sWarp[4];
    int bid = blockIdx.x;
    int g   = bid / (NPG/128);       // NPG/128 = 150
    int blk = bid % (NPG/128);
    int p   = blk*128 + threadIdx.x; // exact: 150*128 == 19200
    int b   = p / T_, t = p % T_;

    const float4* zd4 = (const float4*)g_zd;
    float4 r_lo = zd4[((size_t)g*NPG + p)*2];
    float4 r_hi = zd4[((size_t)g*NPG + p)*2 + 1];
    float4 q_lo = make_float4(0,0,0,0), q_hi = make_float4(0,0,0,0);
    float  sse  = 0.f;
    int codes[NVQ_];

    for (int i = 0; i < NVQ_; i++) {
        __syncthreads();
        {   // cooperative codebook load: 2048 float4
            const float4* src = (const float4*)g_en + (size_t)(g*NVQ_ + i)*K_*2;
            float4* dst = (float4*)sEn;
            for (int j = threadIdx.x; j < K_*2; j += 128) dst[j] = src[j];
        }
        __syncthreads();

        const float4* e4 = (const float4*)sEn;
        float best = -3.0e38f; int bk = 0;
#pragma unroll 4
        for (int k = 0; k < K_; k++) {
            float4 e0 = e4[2*k], e1 = e4[2*k + 1];
            float s0 = r_lo.x * e0.x;
            float s1 = r_lo.y * e0.y;
            s0 = fmaf(r_lo.z, e0.z, s0); s1 = fmaf(r_lo.w, e0.w, s1);
            s0 = fmaf(r_hi.x, e1.x, s0); s1 = fmaf(r_hi.y, e1.y, s1);
            s0 = fmaf(r_hi.z, e1.z, s0); s1 = fmaf(r_hi.w, e1.w, s1);
            float s = s0 + s1;
            if (s > best) { best = s; bk = k; }   // strict > keeps first max (jnp tie rule)
        }
        codes[i] = bk;
        float4 e0 = e4[2*bk], e1 = e4[2*bk + 1];
        r_lo.x -= e0.x; r_lo.y -= e0.y; r_lo.z -= e0.z; r_lo.w -= e0.w;
        r_hi.x -= e1.x; r_hi.y -= e1.y; r_hi.z -= e1.z; r_hi.w -= e1.w;
        q_lo.x += e0.x; q_lo.y += e0.y; q_lo.z += e0.z; q_lo.w += e0.w;
        q_hi.x += e1.x; q_hi.y += e1.y; q_hi.z += e1.z; q_hi.w += e1.w;
        // (residual - q)^2 summed == ||new residual||^2
        float ss = r_lo.x*r_lo.x + r_lo.y*r_lo.y + r_lo.z*r_lo.z + r_lo.w*r_lo.w
                 + r_hi.x*r_hi.x + r_hi.y*r_hi.y + r_hi.z*r_hi.z + r_hi.w*r_hi.w;
        sse += ss;
    }

    // write quantized vector
    float4* zq4 = (float4*)g_zqd;
    zq4[((size_t)g*NPG + p)*2]     = q_lo;
    zq4[((size_t)g*NPG + p)*2 + 1] = q_hi;
    // write codes: indices[b, i, g, t]
#pragma unroll
    for (int i = 0; i < NVQ_; i++)
        out_codes[((size_t)(b*NVQ_ + i)*G_ + g)*T_ + t] = (float)codes[i];

    // deterministic block reduction of sse
#pragma unroll
    for (int off = 16; off > 0; off >>= 1)
        sse += __shfl_down_sync(0xffffffffu, sse, off);
    int lane = threadIdx.x & 31, wid = threadIdx.x >> 5;
    if (lane == 0) sWarp[wid] = sse;
    __syncthreads();
    if (threadIdx.x == 0)
        g_partial[bid] = sWarp[0] + sWarp[1] + sWarp[2] + sWarp[3];
}

// ---------------------------------------------------------------------------
// K4: proj_up fused with post_process (unfold + inverse permute).
// ---------------------------------------------------------------------------
__global__ void k_up(const float* __restrict__ pu, float* __restrict__ out) {
    int n = blockIdx.x * 256 + threadIdx.x;   // grid sized exactly
    int c  = n & 63;
    int m  = n >> 6;
    int w  = m % W_;
    int bh = m / W_;
    int b  = bh / H_, h = bh % H_;
    int t  = w >> 2, o = w & 3;
    int pp = o*FIX_ + c*6 + h;
    int g  = pp >> 9, j = pp & 511;
    const float4* zq4 = (const float4*)(g_zqd + ((size_t)g*NPG + b*T_ + t)*8);
    const float4* pu4 = (const float4*)(pu + (size_t)(g*GD_ + j)*8);
    float4 zl = zq4[0], zh = zq4[1];
    float4 pl = __ldg(pu4), ph = __ldg(pu4 + 1);
    float s0 = zl.x*pl.x, s1 = zl.y*pl.y;
    s0 = fmaf(zl.z, pl.z, s0); s1 = fmaf(zl.w, pl.w, s1);
    s0 = fmaf(zh.x, ph.x, s0); s1 = fmaf(zh.y, ph.y, s1);
    s0 = fmaf(zh.z, ph.z, s0); s1 = fmaf(zh.w, ph.w, s1);
    out[n] = s0 + s1;
}

// ---------------------------------------------------------------------------
// K5: final deterministic loss reduction; cm_loss == cb_loss in forward.
// ---------------------------------------------------------------------------
__global__ void k_final(float* __restrict__ d_out) {
    __shared__ float s[512];
    int tid = threadIdx.x;
    float v = (tid < 450) ? g_partial[tid] : 0.f;
    s[tid] = v; __syncthreads();
    for (int off = 256; off > 0; off >>= 1) {
        if (tid < off) s[tid] += s[tid + off];
        __syncthreads();
    }
    if (tid == 0) {
        float loss = s[0] / (float)(G_ * B_ * T_ * D_);   // /460800
        d_out[ZQ_SIZE + IDX_SIZE]     = loss;   // cm_loss
        d_out[ZQ_SIZE + IDX_SIZE + 1] = loss;   // cb_loss
    }
}

// ---------------------------------------------------------------------------
extern "C" void kernel_launch(void* const* d_in, const int* in_sizes, int n_in,
                              void* d_out, int out_size) {
    const float* z_e = (const float*)d_in[0];
    const float* pd  = (const float*)d_in[1];
    const float* pu  = (const float*)d_in[2];
    const float* cb  = (const float*)d_in[3];
    float* out = (float*)d_out;

    cudaFuncSetAttribute(k_down, cudaFuncAttributeMaxDynamicSharedMemorySize, K2_SMEM);

    k_norm<<<(G_*NVQ_*K_ + 255)/256, 256>>>(cb);
    k_down<<<B_*(T_/8), 256, K2_SMEM>>>(z_e, pd);
    k_rvq<<<G_*(NPG/128), 128>>>(out + ZQ_SIZE);
    k_up<<<ZQ_SIZE/256, 256>>>(pu, out);
    k_final<<<1, 512>>>(out);
}

// round 2
// speedup vs baseline: 1.6104x; 1.6104x over previous
#include <cuda_runtime.h>
#include <math.h>

// Problem constants
#define B_    32
#define H_    6
#define W_    2400
#define C_    64
#define OV_   4
#define G_    3
#define NVQ_  6
#define K_    1024
#define D_    8
#define FIX_  384
#define GD_   512
#define T_    600
#define NPG   (B_*T_)              // 19200
#define ZQ_SIZE  (B_*H_*W_*C_)     // 29491200
#define IDX_SIZE (B_*NVQ_*G_*T_)   // 345600

__device__ float g_en2[G_*NVQ_*K_*D_];   // pair-packed normalized codebooks
__device__ float g_zd [G_*NPG*D_];
__device__ float g_zqd[G_*NPG*D_];
__device__ float g_partial[512];

// ---------------------------------------------------------------------------
// K1: normalize codebook rows AND repack into pair-interleaved layout:
// for pair j (k=2j,2j+1), dim d: g_en2[gi*8192 + j*16 + d*2 + (k&1)]
// ---------------------------------------------------------------------------
__global__ void k_norm(const float* __restrict__ cb) {
    int r = blockIdx.x * blockDim.x + threadIdx.x;
    if (r >= G_*NVQ_*K_) return;
    const float* src = cb + (size_t)r * D_;
    float v[8]; float ss = 0.f;
#pragma unroll
    for (int d = 0; d < 8; d++) { v[d] = src[d]; ss = fmaf(v[d], v[d], ss); }
    float inv = 1.0f / fmaxf(sqrtf(ss), 1e-12f);
    int gi = r >> 10, k = r & 1023;
    int j = k >> 1, half = k & 1;
    float* dst = g_en2 + (size_t)gi*(K_*D_) + j*16 + half;
#pragma unroll
    for (int d = 0; d < 8; d++) dst[d*2] = v[d] * inv;
}

// ---------------------------------------------------------------------------
// K2: pre_process fused with proj_down (unchanged from R1).
// ---------------------------------------------------------------------------
#define SZ_STRIDE 1540
#define PD_STRIDE 520
#define K2_SMEM   ((8*SZ_STRIDE + 24*PD_STRIDE) * 4)

__global__ void k_down(const float* __restrict__ ze, const float* __restrict__ pd) {
    extern __shared__ float sm[];
    float* sZ  = sm;
    float* sPD = sm + 8*SZ_STRIDE;
    int bid  = blockIdx.x;
    int b    = bid / (T_/8);
    int tblk = bid % (T_/8);
    int t0   = tblk * 8;
    int w0   = t0 * 4;
    int tid  = threadIdx.x;

    for (int idx = tid; idx < G_*D_*GD_; idx += 256) {
        int gd = idx >> 9, j = idx & 511;
        sPD[gd*PD_STRIDE + j] = pd[idx];
    }
#pragma unroll
    for (int h = 0; h < 6; h++) {
        const float* src = ze + ((size_t)(b*H_ + h)*W_ + w0) * C_;
        for (int e = tid; e < 32*64; e += 256) {
            int wl = e >> 6, c = e & 63;
            int tl = wl >> 2, o = wl & 3;
            sZ[tl*SZ_STRIDE + o*FIX_ + c*6 + h] = src[e];
        }
    }
    __syncthreads();

    if (tid < 192) {
        int gd = tid >> 3;
        int tl = tid & 7;
        int g  = gd >> 3, d = gd & 7;
        const float4* zr = (const float4*)(sZ + tl*SZ_STRIDE + g*GD_);
        const float4* pr = (const float4*)(sPD + gd*PD_STRIDE);
        float a0 = 0.f, a1 = 0.f;
#pragma unroll 8
        for (int j = 0; j < 128; j += 2) {
            float4 z0 = zr[j],   p0 = pr[j];
            float4 z1 = zr[j+1], p1 = pr[j+1];
            a0 = fmaf(z0.x, p0.x, a0); a1 = fmaf(z0.y, p0.y, a1);
            a0 = fmaf(z0.z, p0.z, a0); a1 = fmaf(z0.w, p0.w, a1);
            a0 = fmaf(z1.x, p1.x, a0); a1 = fmaf(z1.y, p1.y, a1);
            a0 = fmaf(z1.z, p1.z, a0); a1 = fmaf(z1.w, p1.w, a1);
        }
        g_zd[((size_t)g*NPG + b*T_ + t0 + tl)*D_ + d] = a0 + a1;
    }
}

// ---------------------------------------------------------------------------
// K3: residual VQ with packed f32x2 FFMA2 over codeword PAIRS.
// Each FFMA2 half accumulates a different k -> no horizontal add.
// ---------------------------------------------------------------------------
__global__ void __launch_bounds__(128) k_rvq(float* __restrict__ out_codes) {
    __shared__ ulonglong2 sE[K_/2 * 4];   // 512 pairs * 4 u64x2 = 32KB
    __shared__ float sWarp[4];
    int bid = blockIdx.x;
    int g   = bid / (NPG/128);
    int blk = bid % (NPG/128);
    int p   = blk*128 + threadIdx.x;
    int b   = p / T_, t = p % T_;

    const float4* zd4 = (const float4*)g_zd;
    float4 rl = zd4[((size_t)g*NPG + p)*2];
    float4 rh = zd4[((size_t)g*NPG + p)*2 + 1];
    float r[8] = { rl.x, rl.y, rl.z, rl.w, rh.x, rh.y, rh.z, rh.w };
    float q[8] = { 0,0,0,0,0,0,0,0 };
    float sse = 0.f;
    int codes[NVQ_];

    for (int i = 0; i < NVQ_; i++) {
        __syncthreads();
        {
            const float4* src = (const float4*)(g_en2 + (size_t)(g*NVQ_ + i)*(K_*D_));
            float4* dst = (float4*)sE;
            for (int j = threadIdx.x; j < K_*2; j += 128) dst[j] = src[j];
        }
        __syncthreads();

        // broadcast-pack residual into f32x2 regs
        unsigned long long r2[8];
#pragma unroll
        for (int d = 0; d < 8; d++)
            asm("mov.b64 %0, {%1, %1};" : "=l"(r2[d]) : "f"(r[d]));

        float best = -3.0e38f; int bk = 0;
#pragma unroll 4
        for (int j = 0; j < K_/2; j++) {
            ulonglong2 ea = sE[j*4 + 0];
            ulonglong2 eb = sE[j*4 + 1];
            ulonglong2 ec = sE[j*4 + 2];
            ulonglong2 ed = sE[j*4 + 3];
            unsigned long long acc;
            asm("mul.rn.f32x2 %0, %1, %2;"     : "=l"(acc) : "l"(r2[0]), "l"(ea.x));
            asm("fma.rn.f32x2 %0, %1, %2, %0;" : "+l"(acc) : "l"(r2[1]), "l"(ea.y));
            asm("fma.rn.f32x2 %0, %1, %2, %0;" : "+l"(acc) : "l"(r2[2]), "l"(eb.x));
            asm("fma.rn.f32x2 %0, %1, %2, %0;" : "+l"(acc) : "l"(r2[3]), "l"(eb.y));
            asm("fma.rn.f32x2 %0, %1, %2, %0;" : "+l"(acc) : "l"(r2[4]), "l"(ec.x));
            asm("fma.rn.f32x2 %0, %1, %2, %0;" : "+l"(acc) : "l"(r2[5]), "l"(ec.y));
            asm("fma.rn.f32x2 %0, %1, %2, %0;" : "+l"(acc) : "l"(r2[6]), "l"(ed.x));
            asm("fma.rn.f32x2 %0, %1, %2, %0;" : "+l"(acc) : "l"(r2[7]), "l"(ed.y));
            float lo, hi;
            asm("mov.b64 {%0, %1}, %2;" : "=f"(lo), "=f"(hi) : "l"(acc));
            if (lo > best) { best = lo; bk = 2*j; }      // even k first: jnp tie rule
            if (hi > best) { best = hi; bk = 2*j + 1; }
        }
        codes[i] = bk;

        // gather chosen codeword, update residual/quantized/sse
        const float2* ep = (const float2*)sE + (bk >> 1)*8;
        int hsel = bk & 1;
        float ss = 0.f;
#pragma unroll
        for (int d = 0; d < 8; d++) {
            float2 pr = ep[d];
            float ev = hsel ? pr.y : pr.x;
            r[d] -= ev; q[d] += ev;
            ss = fmaf(r[d], r[d], ss);
        }
        sse += ss;
    }

    float4* zq4 = (float4*)g_zqd;
    zq4[((size_t)g*NPG + p)*2]     = make_float4(q[0], q[1], q[2], q[3]);
    zq4[((size_t)g*NPG + p)*2 + 1] = make_float4(q[4], q[5], q[6], q[7]);
#pragma unroll
    for (int i = 0; i < NVQ_; i++)
        out_codes[((size_t)(b*NVQ_ + i)*G_ + g)*T_ + t] = (float)codes[i];

#pragma unroll
    for (int off = 16; off > 0; off >>= 1)
        sse += __shfl_down_sync(0xffffffffu, sse, off);
    int lane = threadIdx.x & 31, wid = threadIdx.x >> 5;
    if (lane == 0) sWarp[wid] = sse;
    __syncthreads();
    if (threadIdx.x == 0)
        g_partial[bid] = sWarp[0] + sWarp[1] + sWarp[2] + sWarp[3];
}

// ---------------------------------------------------------------------------
// K4: proj_up fused with post_process. Warp = (o,h,c-half); lanes = consecutive
// c (coalesced stores); pu held in registers, reused across 25 t's; zqd
// broadcast from smem. Kills the 64B-per-output L1 gather of R1.
// ---------------------------------------------------------------------------
#define TT 25
__global__ void __launch_bounds__(256) k_up(const float* __restrict__ pu, float* __restrict__ out) {
    __shared__ float sZ[G_*TT*D_];   // 600 floats
    int bid  = blockIdx.x;
    int b    = bid / (T_/TT);        // T_/TT = 24
    int tile = bid % (T_/TT);
    int t0   = tile * TT;
    int tid  = threadIdx.x;

    for (int idx = tid; idx < G_*TT*D_; idx += 256) {
        int g  = idx / (TT*D_);
        int rr = idx % (TT*D_);
        sZ[idx] = g_zqd[((size_t)g*NPG + b*T_ + t0)*D_ + rr];
    }
    __syncthreads();

    int wid = tid >> 5, lane = tid & 31;
    for (int task = wid; task < 48; task += 8) {
        int o   = task / 12;
        int rem = task % 12;
        int h   = rem >> 1;
        int ch  = rem & 1;
        int c   = ch*32 + lane;
        int pp  = o*FIX_ + c*6 + h;
        int g   = pp >> 9;
        const float4* pu4 = (const float4*)pu + (size_t)pp*2;
        float4 pl = __ldg(pu4), ph = __ldg(pu4 + 1);
        float* op = out + ((size_t)(b*H_ + h)*W_ + 4*t0 + o)*C_ + c;
        const float4* zb = (const float4*)(sZ + g*(TT*D_));
#pragma unroll 5
        for (int tl = 0; tl < TT; tl++) {
            float4 zl = zb[tl*2], zh = zb[tl*2 + 1];
            float s0 = zl.x*pl.x, s1 = zl.y*pl.y;
            s0 = fmaf(zl.z, pl.z, s0); s1 = fmaf(zl.w, pl.w, s1);
            s0 = fmaf(zh.x, ph.x, s0); s1 = fmaf(zh.y, ph.y, s1);
            s0 = fmaf(zh.z, ph.z, s0); s1 = fmaf(zh.w, ph.w, s1);
            op[(size_t)tl*4*C_] = s0 + s1;
        }
    }
}

// ---------------------------------------------------------------------------
// K5: final deterministic loss reduction.
// ---------------------------------------------------------------------------
__global__ void k_final(float* __restrict__ d_out) {
    __shared__ float s[512];
    int tid = threadIdx.x;
    float v = (tid < 450) ? g_partial[tid] : 0.f;
    s[tid] = v; __syncthreads();
    for (int off = 256; off > 0; off >>= 1) {
        if (tid < off) s[tid] += s[tid + off];
        __syncthreads();
    }
    if (tid == 0) {
        float loss = s[0] / (float)(G_ * B_ * T_ * D_);
        d_out[ZQ_SIZE + IDX_SIZE]     = loss;
        d_out[ZQ_SIZE + IDX_SIZE + 1] = loss;
    }
}

// ---------------------------------------------------------------------------
extern "C" void kernel_launch(void* const* d_in, const int* in_sizes, int n_in,
                              void* d_out, int out_size) {
    const float* z_e = (const float*)d_in[0];
    const float* pd  = (const float*)d_in[1];
    const float* pu  = (const float*)d_in[2];
    const float* cb  = (const float*)d_in[3];
    float* out = (float*)d_out;

    cudaFuncSetAttribute(k_down, cudaFuncAttributeMaxDynamicSharedMemorySize, K2_SMEM);

    k_norm<<<(G_*NVQ_*K_ + 255)/256, 256>>>(cb);
    k_down<<<B_*(T_/8), 256, K2_SMEM>>>(z_e, pd);
    k_rvq<<<G_*(NPG/128), 128>>>(out + ZQ_SIZE);
    k_up<<<B_*(T_/TT), 256>>>(pu, out);
    k_final<<<1, 512>>>(out);
}